// round 2
// baseline (speedup 1.0000x reference)
#include <cuda_runtime.h>
#include <cuda_bf16.h>
#include <cstdint>

// Problem constants
#define BB 32
#define CC 5
#define HH 50
#define SS 20     // seq len (s and t)
#define EE 300
#define KK 20
#define F4N 75    // EE/4
#define NCS 100   // C*S
#define CSTRIDE 160   // cdd chunk row stride in floats (640B = 5*128B, conflict-free)
#define F4C0 38   // chunk0 float4 count (e 0..151)
#define F4C1 37   // chunk1 float4 count (e 152..299)

// -log2(e) / (2*sigma^2)
#define NC_STD  (-72.134752f)
#define NC_LAST (-721347.52f)

struct Smem {
    float hisT[EE * SS];        // [e][t] 24000B
    float cddc[NCS * CSTRIDE];  // chunked candidate rows, 64000B
    float simbuf[NCS * SS];     // 8000B
    float sumc[NCS];
    float invc[NCS];
    float invh[SS];
    float padh[SS];
    float padc[NCS];
    float wv[KK];
    float cont[256];
};

__device__ float g_partial[BB * HH * CC];

__device__ __forceinline__ float ex2_approx(float x) {
    float r;
    asm("ex2.approx.ftz.f32 %0, %1;" : "=f"(r) : "f"(x));
    return r;
}

// Accumulate 4 rows x 20 t over float4 range [f0,f1) of this chunk.
// cbase points at row r0 of cddc; his e-index = (fglob + f)*4 + j.
__device__ __forceinline__ void accum_tile(const float* __restrict__ cbase,
                                           const float* __restrict__ hisT,
                                           int f0, int f1, int fglob,
                                           float (&acc)[4][SS])
{
    for (int f = f0; f < f1; ++f) {
        float4 a0 = *reinterpret_cast<const float4*>(cbase + 0 * CSTRIDE + f * 4);
        float4 a1 = *reinterpret_cast<const float4*>(cbase + 1 * CSTRIDE + f * 4);
        float4 a2 = *reinterpret_cast<const float4*>(cbase + 2 * CSTRIDE + f * 4);
        float4 a3 = *reinterpret_cast<const float4*>(cbase + 3 * CSTRIDE + f * 4);
        const float* hb = hisT + (fglob + f) * 4 * SS;
        #pragma unroll
        for (int j = 0; j < 4; ++j) {
            float v0 = (j == 0) ? a0.x : (j == 1) ? a0.y : (j == 2) ? a0.z : a0.w;
            float v1 = (j == 0) ? a1.x : (j == 1) ? a1.y : (j == 2) ? a1.z : a1.w;
            float v2 = (j == 0) ? a2.x : (j == 1) ? a2.y : (j == 2) ? a2.z : a2.w;
            float v3 = (j == 0) ? a3.x : (j == 1) ? a3.y : (j == 2) ? a3.z : a3.w;
            const float4* ht = reinterpret_cast<const float4*>(hb + j * SS);
            #pragma unroll
            for (int q = 0; q < 5; ++q) {
                float4 h4 = ht[q];
                acc[0][q*4+0] = fmaf(v0, h4.x, acc[0][q*4+0]);
                acc[0][q*4+1] = fmaf(v0, h4.y, acc[0][q*4+1]);
                acc[0][q*4+2] = fmaf(v0, h4.z, acc[0][q*4+2]);
                acc[0][q*4+3] = fmaf(v0, h4.w, acc[0][q*4+3]);
                acc[1][q*4+0] = fmaf(v1, h4.x, acc[1][q*4+0]);
                acc[1][q*4+1] = fmaf(v1, h4.y, acc[1][q*4+1]);
                acc[1][q*4+2] = fmaf(v1, h4.z, acc[1][q*4+2]);
                acc[1][q*4+3] = fmaf(v1, h4.w, acc[1][q*4+3]);
                acc[2][q*4+0] = fmaf(v2, h4.x, acc[2][q*4+0]);
                acc[2][q*4+1] = fmaf(v2, h4.y, acc[2][q*4+1]);
                acc[2][q*4+2] = fmaf(v2, h4.z, acc[2][q*4+2]);
                acc[2][q*4+3] = fmaf(v2, h4.w, acc[2][q*4+3]);
                acc[3][q*4+0] = fmaf(v3, h4.x, acc[3][q*4+0]);
                acc[3][q*4+1] = fmaf(v3, h4.y, acc[3][q*4+1]);
                acc[3][q*4+2] = fmaf(v3, h4.z, acc[3][q*4+2]);
                acc[3][q*4+3] = fmaf(v3, h4.w, acc[3][q*4+3]);
            }
        }
    }
}

__global__ __launch_bounds__(256, 2)
void knrm_main(const int* __restrict__ cand, const int* __restrict__ clk,
               const float* __restrict__ cpad, const float* __restrict__ hpad,
               const float* __restrict__ emb, const float* __restrict__ ltr_w)
{
    extern __shared__ float smraw[];
    Smem* sm = reinterpret_cast<Smem*>(smraw);
    const int tid = threadIdx.x;
    const int wid = tid >> 5, lane = tid & 31;
    const int b = blockIdx.x / HH;
    const int h = blockIdx.x % HH;

    // Phase A thread mapping: tile (4 rows) x 8 e-chunk lanes; warps 0..6
    const int tileRaw = tid >> 3;
    const int tile = (tileRaw < 25) ? tileRaw : 24;   // clamp dummies (warp 6 lanes 8..31 run tile24)
    const int ec = tid & 7;
    const bool phaseA = (tid < 224);

    float acc[4][SS];
    #pragma unroll
    for (int r = 0; r < 4; ++r)
        #pragma unroll
        for (int t = 0; t < SS; ++t) acc[r][t] = 0.f;

    // -------- gather: hisT (full, transposed) + cdd chunk0 --------
    for (int i = tid; i < SS * F4N; i += 256) {
        int t = i / F4N, f = i % F4N;
        int tok = clk[(b * HH + h) * SS + t];
        float4 v = *reinterpret_cast<const float4*>(emb + (size_t)tok * EE + f * 4);
        sm->hisT[(f * 4 + 0) * SS + t] = v.x;
        sm->hisT[(f * 4 + 1) * SS + t] = v.y;
        sm->hisT[(f * 4 + 2) * SS + t] = v.z;
        sm->hisT[(f * 4 + 3) * SS + t] = v.w;
    }
    for (int i = tid; i < NCS * F4C0; i += 256) {
        int r = i / F4C0, f = i % F4C0;
        int tok = cand[b * NCS + r];
        float4 v = *reinterpret_cast<const float4*>(emb + (size_t)tok * EE + f * 4);
        *reinterpret_cast<float4*>(sm->cddc + r * CSTRIDE + f * 4) = v;
    }
    if (tid < SS)  sm->padh[tid] = hpad[(b * HH + h) * SS + tid];
    if (tid < KK)  sm->wv[tid]   = ltr_w[h * KK + tid];
    for (int i = tid; i < NCS; i += 256) sm->padc[i] = cpad[b * NCS + i];
    __syncthreads();

    // -------- his norms (160 threads) + cdd sumsq chunk0 --------
    if (tid < SS * 8) {
        int t = tid >> 3, p = tid & 7;
        float ss = 0.f;
        for (int e = p; e < EE; e += 8) {
            float v = sm->hisT[e * SS + t];
            ss = fmaf(v, v, ss);
        }
        ss += __shfl_down_sync(0xffffffffu, ss, 4);
        ss += __shfl_down_sync(0xffffffffu, ss, 2);
        ss += __shfl_down_sync(0xffffffffu, ss, 1);
        if (p == 0) sm->invh[t] = 1.0f / fmaxf(sqrtf(ss), 1e-12f);
    }
    for (int r = wid; r < NCS; r += 8) {
        float ss = 0.f;
        for (int e = lane; e < F4C0 * 4; e += 32) {
            float v = sm->cddc[r * CSTRIDE + e];
            ss = fmaf(v, v, ss);
        }
        #pragma unroll
        for (int o = 16; o; o >>= 1) ss += __shfl_down_sync(0xffffffffu, ss, o);
        if (lane == 0) sm->sumc[r] = ss;
    }

    // -------- phase A accumulate chunk0 --------
    if (phaseA) {
        int f0 = (ec * F4C0) >> 3, f1 = ((ec + 1) * F4C0) >> 3;
        accum_tile(sm->cddc + tile * 4 * CSTRIDE, sm->hisT, f0, f1, 0, acc);
    }
    __syncthreads();   // all chunk0 reads done

    // -------- gather cdd chunk1 --------
    for (int i = tid; i < NCS * F4C1; i += 256) {
        int r = i / F4C1, f = i % F4C1;
        int tok = cand[b * NCS + r];
        float4 v = *reinterpret_cast<const float4*>(emb + (size_t)tok * EE + (F4C0 + f) * 4);
        *reinterpret_cast<float4*>(sm->cddc + r * CSTRIDE + f * 4) = v;
    }
    __syncthreads();

    // -------- cdd sumsq chunk1 -> invc --------
    for (int r = wid; r < NCS; r += 8) {
        float ss = 0.f;
        for (int e = lane; e < F4C1 * 4; e += 32) {
            float v = sm->cddc[r * CSTRIDE + e];
            ss = fmaf(v, v, ss);
        }
        #pragma unroll
        for (int o = 16; o; o >>= 1) ss += __shfl_down_sync(0xffffffffu, ss, o);
        if (lane == 0) sm->invc[r] = 1.0f / fmaxf(sqrtf(sm->sumc[r] + ss), 1e-12f);
    }

    // -------- phase A accumulate chunk1 --------
    if (phaseA) {
        int f0 = (ec * F4C1) >> 3, f1 = ((ec + 1) * F4C1) >> 3;
        accum_tile(sm->cddc + tile * 4 * CSTRIDE, sm->hisT, f0, f1, F4C0, acc);
    }
    __syncthreads();   // invc visible to everyone

    // -------- reduce over 8 e-lanes, scale, write simbuf --------
    if (phaseA) {
        #pragma unroll
        for (int r = 0; r < 4; ++r)
            #pragma unroll
            for (int t = 0; t < SS; ++t) {
                acc[r][t] += __shfl_down_sync(0xffffffffu, acc[r][t], 4);
                acc[r][t] += __shfl_down_sync(0xffffffffu, acc[r][t], 2);
                acc[r][t] += __shfl_down_sync(0xffffffffu, acc[r][t], 1);
            }
        if (ec == 0 && tid < 200) {
            int r0 = tile * 4;
            #pragma unroll
            for (int r = 0; r < 4; ++r) {
                float ic = sm->invc[r0 + r];
                #pragma unroll
                for (int t = 0; t < SS; ++t)
                    sm->simbuf[(r0 + r) * SS + t] = acc[r][t] * ic * sm->invh[t];
            }
        }
    }
    __syncthreads();

    // -------- phase B: Gaussian pooling + log + weight dot --------
    float contrib = 0.0f;
    if (tid < 200) {
        int cs = tid >> 1, kh = tid & 1;
        float ps[10];
        #pragma unroll
        for (int k = 0; k < 10; ++k) ps[k] = 0.f;
        for (int t = 0; t < SS; ++t) {
            float s  = sm->simbuf[cs * SS + t];
            float pt = sm->padh[t];
            #pragma unroll
            for (int k = 0; k < 10; ++k) {
                int kk = kh * 10 + k;
                float mu = -0.9f + 0.1f * (float)kk;
                float nc = (kh == 1 && k == 9) ? NC_LAST : NC_STD;
                float d = s - mu;
                float a = d * d * nc;
                ps[k] = fmaf(pt, ex2_approx(a), ps[k]);
            }
        }
        float accw = 0.f;
        #pragma unroll
        for (int k = 0; k < 10; ++k) {
            float lp = __logf(fmaxf(ps[k], 1e-10f));
            accw = fmaf(lp, sm->wv[kh * 10 + k], accw);
        }
        contrib = accw * 0.01f * sm->padc[cs];
    }
    sm->cont[tid] = contrib;
    __syncthreads();

    if (tid < CC) {
        float s = 0.f;
        #pragma unroll 8
        for (int i = 0; i < 40; ++i) s += sm->cont[tid * 40 + i];
        g_partial[(b * HH + h) * CC + tid] = s;
    }
}

__global__ void knrm_final(const float* __restrict__ ltr_b, float* __restrict__ out)
{
    __shared__ float sc[BB * CC];
    int tid = threadIdx.x;
    if (tid < BB * CC) {
        int b = tid / CC, c = tid % CC;
        float s = ltr_b[0];
        for (int hh = 0; hh < HH; ++hh)
            s += g_partial[(b * HH + hh) * CC + c];
        sc[tid] = s;
    }
    __syncthreads();
    if (tid < BB * CC) {
        int b = tid / CC;
        float m = -1e30f;
        #pragma unroll
        for (int c2 = 0; c2 < CC; ++c2) m = fmaxf(m, sc[b * CC + c2]);
        float se = 0.f;
        #pragma unroll
        for (int c2 = 0; c2 < CC; ++c2) se += expf(sc[b * CC + c2] - m);
        out[tid] = sc[tid] - m - logf(se);
    }
}

extern "C" void kernel_launch(void* const* d_in, const int* in_sizes, int n_in,
                              void* d_out, int out_size)
{
    const int*   cand = (const int*)  d_in[0];
    const int*   clk  = (const int*)  d_in[1];
    const float* cpad = (const float*)d_in[2];
    const float* hpad = (const float*)d_in[3];
    const float* emb  = (const float*)d_in[4];
    const float* w    = (const float*)d_in[5];
    const float* bb   = (const float*)d_in[6];

    size_t smem = sizeof(Smem);
    cudaFuncSetAttribute(knrm_main, cudaFuncAttributeMaxDynamicSharedMemorySize, (int)smem);

    knrm_main<<<BB * HH, 256, smem>>>(cand, clk, cpad, hpad, emb, w);
    knrm_final<<<1, 192>>>(bb, (float*)d_out);
}

// round 4
// speedup vs baseline: 1.2698x; 1.2698x over previous
#include <cuda_runtime.h>
#include <cuda_bf16.h>
#include <cstdint>

#define BB 32
#define CC 5
#define HH 50
#define SS 20
#define EE 300
#define KK 20
#define F4N 75
#define NCS 100
#define ROWSTRIDE 160        // floats between rows within a 4-row group
#define GRPSTRIDE 648        // floats between 4-row groups (bank-staggered: 648 mod 32 = 8)
#define NGRP 25
#define F4C0 38              // chunk0 float4 per row (e 0..151)
#define F4C1 37              // chunk1 float4 per row (e 152..299)

#define NC_STD  (-72.134752f)
#define NC_LAST (-721347.52f)

struct Smem {
    float hisT[EE * SS];                // [e][t]  24000B
    float cddc[NGRP * GRPSTRIDE];       // 64800B
    float simbuf[NCS * SS];             // 8000B
    float sumc[NCS];
    float invc[NCS];
    float invh[SS];
    float padh[SS];
    float padc[NCS];
    float wv[KK];
    float cont[256];
};

__device__ float g_partial[BB * HH * CC];

__device__ __forceinline__ float ex2_approx(float x) {
    float r;
    asm("ex2.approx.ftz.f32 %0, %1;" : "=f"(r) : "f"(x));
    return r;
}
__device__ __forceinline__ void fma2(unsigned long long& acc,
                                     unsigned long long a, unsigned long long b) {
    asm("fma.rn.f32x2 %0, %1, %2, %0;" : "+l"(acc) : "l"(a), "l"(b));
}
__device__ __forceinline__ unsigned long long dupf(float x) {
    unsigned long long r;
    asm("mov.b64 %0, {%1, %1};" : "=l"(r) : "f"(x));
    return r;
}

__device__ __forceinline__ void accum_chunk(const float* __restrict__ cbase,
                                            const float* __restrict__ hisT,
                                            int ec, int f4cnt, int fglob,
                                            unsigned long long (&acc)[4][10])
{
    for (int f = ec; f < f4cnt; f += 8) {
        float4 a0 = *reinterpret_cast<const float4*>(cbase + 0 * ROWSTRIDE + f * 4);
        float4 a1 = *reinterpret_cast<const float4*>(cbase + 1 * ROWSTRIDE + f * 4);
        float4 a2 = *reinterpret_cast<const float4*>(cbase + 2 * ROWSTRIDE + f * 4);
        float4 a3 = *reinterpret_cast<const float4*>(cbase + 3 * ROWSTRIDE + f * 4);
        const float* hb = hisT + (fglob + f) * 4 * SS;
        #pragma unroll
        for (int j = 0; j < 4; ++j) {
            float v0 = (j == 0) ? a0.x : (j == 1) ? a0.y : (j == 2) ? a0.z : a0.w;
            float v1 = (j == 0) ? a1.x : (j == 1) ? a1.y : (j == 2) ? a1.z : a1.w;
            float v2 = (j == 0) ? a2.x : (j == 1) ? a2.y : (j == 2) ? a2.z : a2.w;
            float v3 = (j == 0) ? a3.x : (j == 1) ? a3.y : (j == 2) ? a3.z : a3.w;
            unsigned long long d0 = dupf(v0), d1 = dupf(v1), d2 = dupf(v2), d3 = dupf(v3);
            const ulonglong2* hp = reinterpret_cast<const ulonglong2*>(hb + j * SS);
            #pragma unroll
            for (int q = 0; q < 5; ++q) {
                ulonglong2 hv = hp[q];
                fma2(acc[0][q * 2 + 0], d0, hv.x);
                fma2(acc[0][q * 2 + 1], d0, hv.y);
                fma2(acc[1][q * 2 + 0], d1, hv.x);
                fma2(acc[1][q * 2 + 1], d1, hv.y);
                fma2(acc[2][q * 2 + 0], d2, hv.x);
                fma2(acc[2][q * 2 + 1], d2, hv.y);
                fma2(acc[3][q * 2 + 0], d3, hv.x);
                fma2(acc[3][q * 2 + 1], d3, hv.y);
            }
        }
    }
}

__global__ __launch_bounds__(256, 2)
void knrm_main(const int* __restrict__ cand, const int* __restrict__ clk,
               const float* __restrict__ cpad, const float* __restrict__ hpad,
               const float* __restrict__ emb, const float* __restrict__ ltr_w)
{
    extern __shared__ float smraw[];
    Smem* sm = reinterpret_cast<Smem*>(smraw);
    const int tid = threadIdx.x;
    const int wid = tid >> 5, lane = tid & 31;
    const int b = blockIdx.x / HH;
    const int h = blockIdx.x % HH;

    // Phase A mapping: tile = wid*4 + (lane&3)  (row group), ec = lane>>2
    const int tileIdx = wid * 4 + (lane & 3);
    const int tileC = (tileIdx < NGRP) ? tileIdx : (NGRP - 1);
    const int ec = lane >> 2;

    unsigned long long acc[4][10];
    #pragma unroll
    for (int r = 0; r < 4; ++r)
        #pragma unroll
        for (int p = 0; p < 10; ++p) acc[r][p] = 0ull;

    // -------- gather: hisT (transposed, full E) + cdd chunk0 --------
    for (int i = tid; i < SS * F4N; i += 256) {
        int t = i / F4N, f = i % F4N;
        int tok = clk[(b * HH + h) * SS + t];
        float4 v = *reinterpret_cast<const float4*>(emb + (size_t)tok * EE + f * 4);
        sm->hisT[(f * 4 + 0) * SS + t] = v.x;
        sm->hisT[(f * 4 + 1) * SS + t] = v.y;
        sm->hisT[(f * 4 + 2) * SS + t] = v.z;
        sm->hisT[(f * 4 + 3) * SS + t] = v.w;
    }
    for (int i = tid; i < NCS * F4C0; i += 256) {
        int r = i / F4C0, f = i % F4C0;
        int tok = cand[b * NCS + r];
        float4 v = *reinterpret_cast<const float4*>(emb + (size_t)tok * EE + f * 4);
        *reinterpret_cast<float4*>(sm->cddc + (r >> 2) * GRPSTRIDE + (r & 3) * ROWSTRIDE + f * 4) = v;
    }
    if (tid < SS)  sm->padh[tid] = hpad[(b * HH + h) * SS + tid];
    if (tid < KK)  sm->wv[tid]   = ltr_w[h * KK + tid];
    for (int i = tid; i < NCS; i += 256) sm->padc[i] = cpad[b * NCS + i];
    __syncthreads();

    // -------- his norms + cdd sumsq chunk0 --------
    if (tid < SS * 8) {
        int t = tid >> 3, p = tid & 7;
        float ss = 0.f;
        for (int e = p; e < EE; e += 8) {
            float v = sm->hisT[e * SS + t];
            ss = fmaf(v, v, ss);
        }
        ss += __shfl_down_sync(0xffffffffu, ss, 4);
        ss += __shfl_down_sync(0xffffffffu, ss, 2);
        ss += __shfl_down_sync(0xffffffffu, ss, 1);
        if (p == 0) sm->invh[t] = 1.0f / fmaxf(sqrtf(ss), 1e-12f);
    }
    for (int r = wid; r < NCS; r += 8) {
        const float* rb = sm->cddc + (r >> 2) * GRPSTRIDE + (r & 3) * ROWSTRIDE;
        float ss = 0.f;
        for (int e = lane; e < F4C0 * 4; e += 32) {
            float v = rb[e];
            ss = fmaf(v, v, ss);
        }
        #pragma unroll
        for (int o = 16; o; o >>= 1) ss += __shfl_down_sync(0xffffffffu, ss, o);
        if (lane == 0) sm->sumc[r] = ss;
    }

    // -------- phase A chunk0 --------
    accum_chunk(sm->cddc + tileC * GRPSTRIDE, sm->hisT, ec, F4C0, 0, acc);
    __syncthreads();

    // -------- gather cdd chunk1 --------
    for (int i = tid; i < NCS * F4C1; i += 256) {
        int r = i / F4C1, f = i % F4C1;
        int tok = cand[b * NCS + r];
        float4 v = *reinterpret_cast<const float4*>(emb + (size_t)tok * EE + (F4C0 + f) * 4);
        *reinterpret_cast<float4*>(sm->cddc + (r >> 2) * GRPSTRIDE + (r & 3) * ROWSTRIDE + f * 4) = v;
    }
    __syncthreads();

    // -------- cdd sumsq chunk1 -> invc --------
    for (int r = wid; r < NCS; r += 8) {
        const float* rb = sm->cddc + (r >> 2) * GRPSTRIDE + (r & 3) * ROWSTRIDE;
        float ss = 0.f;
        for (int e = lane; e < F4C1 * 4; e += 32) {
            float v = rb[e];
            ss = fmaf(v, v, ss);
        }
        #pragma unroll
        for (int o = 16; o; o >>= 1) ss += __shfl_down_sync(0xffffffffu, ss, o);
        if (lane == 0) sm->invc[r] = 1.0f / fmaxf(sqrtf(sm->sumc[r] + ss), 1e-12f);
    }

    // -------- phase A chunk1 --------
    accum_chunk(sm->cddc + tileC * GRPSTRIDE, sm->hisT, ec, F4C1, F4C0, acc);
    __syncthreads();   // invc ready

    // -------- reduce over ec (sum lanes {lane, lane+4, ..., lane+28} into lanes 0-3) --------
    #pragma unroll
    for (int o = 16; o >= 4; o >>= 1) {
        #pragma unroll
        for (int r = 0; r < 4; ++r)
            #pragma unroll
            for (int p = 0; p < 10; ++p) {
                unsigned long long other = __shfl_down_sync(0xffffffffu, acc[r][p], o);
                float2 a = *reinterpret_cast<float2*>(&acc[r][p]);
                float2 bo = *reinterpret_cast<float2*>(&other);
                a.x += bo.x; a.y += bo.y;
                acc[r][p] = *reinterpret_cast<unsigned long long*>(&a);
            }
    }
    if (lane < 4 && tileIdx < NGRP) {
        int r0 = tileIdx * 4;
        #pragma unroll
        for (int r = 0; r < 4; ++r) {
            float ic = sm->invc[r0 + r];
            #pragma unroll
            for (int p = 0; p < 10; ++p) {
                float2 a = *reinterpret_cast<float2*>(&acc[r][p]);
                int t0 = p * 2;
                sm->simbuf[(r0 + r) * SS + t0 + 0] = a.x * ic * sm->invh[t0 + 0];
                sm->simbuf[(r0 + r) * SS + t0 + 1] = a.y * ic * sm->invh[t0 + 1];
            }
        }
    }
    __syncthreads();

    // -------- phase B --------
    float contrib = 0.0f;
    if (tid < 200) {
        int cs = tid >> 1, kh = tid & 1;
        float ps[10];
        #pragma unroll
        for (int k = 0; k < 10; ++k) ps[k] = 0.f;
        for (int t = 0; t < SS; ++t) {
            float s  = sm->simbuf[cs * SS + t];
            float pt = sm->padh[t];
            #pragma unroll
            for (int k = 0; k < 10; ++k) {
                int kk = kh * 10 + k;
                float mu = -0.9f + 0.1f * (float)kk;
                float nc = (kh == 1 && k == 9) ? NC_LAST : NC_STD;
                float d = s - mu;
                ps[k] = fmaf(pt, ex2_approx(d * d * nc), ps[k]);
            }
        }
        float accw = 0.f;
        #pragma unroll
        for (int k = 0; k < 10; ++k) {
            float lp = __logf(fmaxf(ps[k], 1e-10f));
            accw = fmaf(lp, sm->wv[kh * 10 + k], accw);
        }
        contrib = accw * 0.01f * sm->padc[cs];
    }
    sm->cont[tid] = contrib;
    __syncthreads();

    if (tid < CC) {
        float s = 0.f;
        #pragma unroll 8
        for (int i = 0; i < 40; ++i) s += sm->cont[tid * 40 + i];
        g_partial[(b * HH + h) * CC + tid] = s;
    }
}

__global__ void knrm_final(const float* __restrict__ ltr_b, float* __restrict__ out)
{
    __shared__ float sc[BB * CC];
    int tid = threadIdx.x;
    if (tid < BB * CC) {
        int b = tid / CC, c = tid % CC;
        float s = ltr_b[0];
        for (int hh = 0; hh < HH; ++hh)
            s += g_partial[(b * HH + hh) * CC + c];
        sc[tid] = s;
    }
    __syncthreads();
    if (tid < BB * CC) {
        int b = tid / CC;
        float m = -1e30f;
        #pragma unroll
        for (int c2 = 0; c2 < CC; ++c2) m = fmaxf(m, sc[b * CC + c2]);
        float se = 0.f;
        #pragma unroll
        for (int c2 = 0; c2 < CC; ++c2) se += expf(sc[b * CC + c2] - m);
        out[tid] = sc[tid] - m - logf(se);
    }
}

// ncu phasing dummies: with 5 launches per iteration, capture -s 5 -c 1 lands
// on launch #6 == knrm_main (we need its profile, not knrm_final's).
__global__ void knrm_nop() {}

extern "C" void kernel_launch(void* const* d_in, const int* in_sizes, int n_in,
                              void* d_out, int out_size)
{
    const int*   cand = (const int*)  d_in[0];
    const int*   clk  = (const int*)  d_in[1];
    const float* cpad = (const float*)d_in[2];
    const float* hpad = (const float*)d_in[3];
    const float* emb  = (const float*)d_in[4];
    const float* w    = (const float*)d_in[5];
    const float* bb   = (const float*)d_in[6];

    size_t smem = sizeof(Smem);
    cudaFuncSetAttribute(knrm_main, cudaFuncAttributeMaxDynamicSharedMemorySize, (int)smem);

    knrm_main<<<BB * HH, 256, smem>>>(cand, clk, cpad, hpad, emb, w);
    knrm_final<<<1, 192>>>(bb, (float*)d_out);
    knrm_nop<<<1, 32>>>();
    knrm_nop<<<1, 32>>>();
    knrm_nop<<<1, 32>>>();
}

// round 5
// speedup vs baseline: 1.4979x; 1.1796x over previous
#include <cuda_runtime.h>
#include <cuda_bf16.h>
#include <cstdint>

#define BB 32
#define CC 5
#define HH 50
#define SS 20
#define EE 300
#define KK 20
#define F4N 75
#define NCS 100
#define NGRP2 50             // 2-row groups
#define ROWOFF 152           // floats: row1 offset within group (= chunk capacity 38 float4)
#define GRPSTRIDE 324        // floats between groups; 324 mod 32 = 4 -> phase banks 16B*{0..7}
#define F4C0 38              // chunk0 float4 per row (e 0..151)
#define F4C1 37              // chunk1 float4 per row (e 152..299)

#define NC_STD  (-72.134752f)
#define NC_LAST (-721347.52f)

struct Smem {
    float hisT[EE * SS];                // [e][t] 24000B
    float cddc[NGRP2 * GRPSTRIDE];      // 64800B
    float simbuf[NCS * SS];             // 8000B
    float sumc[NCS];
    float invc[NCS];
    float invh[SS];
    float padh[SS];
    float padc[NCS];
    float wv[KK];
    float cont[256];
};

__device__ float g_partial[BB * HH * CC];

__device__ __forceinline__ float ex2_approx(float x) {
    float r;
    asm("ex2.approx.ftz.f32 %0, %1;" : "=f"(r) : "f"(x));
    return r;
}
__device__ __forceinline__ void fma2(unsigned long long& acc,
                                     unsigned long long a, unsigned long long b) {
    asm("fma.rn.f32x2 %0, %1, %2, %0;" : "+l"(acc) : "l"(a), "l"(b));
}
__device__ __forceinline__ unsigned long long dupf(float x) {
    unsigned long long r;
    asm("mov.b64 %0, {%1, %1};" : "=l"(r) : "f"(x));
    return r;
}

// 2 rows x 20 t, f = ec + 4i over [0, f4cnt)
__device__ __forceinline__ void accum_chunk(const float* __restrict__ cbase,
                                            const float* __restrict__ hisT,
                                            int ec, int f4cnt, int fglob,
                                            unsigned long long (&acc)[2][10])
{
    for (int f = ec; f < f4cnt; f += 4) {
        float4 a0 = *reinterpret_cast<const float4*>(cbase + f * 4);
        float4 a1 = *reinterpret_cast<const float4*>(cbase + ROWOFF + f * 4);
        const float* hb = hisT + (fglob + f) * 4 * SS;
        #pragma unroll
        for (int j = 0; j < 4; ++j) {
            float v0 = (j == 0) ? a0.x : (j == 1) ? a0.y : (j == 2) ? a0.z : a0.w;
            float v1 = (j == 0) ? a1.x : (j == 1) ? a1.y : (j == 2) ? a1.z : a1.w;
            unsigned long long d0 = dupf(v0), d1 = dupf(v1);
            const ulonglong2* hp = reinterpret_cast<const ulonglong2*>(hb + j * SS);
            #pragma unroll
            for (int q = 0; q < 5; ++q) {
                ulonglong2 hv = hp[q];
                fma2(acc[0][q * 2 + 0], d0, hv.x);
                fma2(acc[0][q * 2 + 1], d0, hv.y);
                fma2(acc[1][q * 2 + 0], d1, hv.x);
                fma2(acc[1][q * 2 + 1], d1, hv.y);
            }
        }
    }
}

__global__ __launch_bounds__(256, 2)
void knrm_main(const int* __restrict__ cand, const int* __restrict__ clk,
               const float* __restrict__ cpad, const float* __restrict__ hpad,
               const float* __restrict__ emb, const float* __restrict__ ltr_w)
{
    extern __shared__ float smraw[];
    Smem* sm = reinterpret_cast<Smem*>(smraw);
    const int tid = threadIdx.x;
    const int wid = tid >> 5, lane = tid & 31;
    const int b = blockIdx.x / HH;
    const int h = blockIdx.x % HH;

    // Phase A mapping: lane = ec*8 + g (ec-major); group = wid*8 + g
    const int ec = lane >> 3;
    const int g  = lane & 7;
    const int grp = wid * 8 + g;                  // 0..63, active < 50
    const int grpC = (grp < NGRP2) ? grp : (NGRP2 - 1);

    unsigned long long acc[2][10];
    #pragma unroll
    for (int r = 0; r < 2; ++r)
        #pragma unroll
        for (int p = 0; p < 10; ++p) acc[r][p] = 0ull;

    // -------- gather: hisT (transposed) + cdd chunk0 --------
    for (int i = tid; i < SS * F4N; i += 256) {
        int t = i / F4N, f = i % F4N;
        int tok = clk[(b * HH + h) * SS + t];
        float4 v = *reinterpret_cast<const float4*>(emb + (size_t)tok * EE + f * 4);
        sm->hisT[(f * 4 + 0) * SS + t] = v.x;
        sm->hisT[(f * 4 + 1) * SS + t] = v.y;
        sm->hisT[(f * 4 + 2) * SS + t] = v.z;
        sm->hisT[(f * 4 + 3) * SS + t] = v.w;
    }
    for (int i = tid; i < NCS * F4C0; i += 256) {
        int r = i / F4C0, f = i % F4C0;
        int tok = cand[b * NCS + r];
        float4 v = *reinterpret_cast<const float4*>(emb + (size_t)tok * EE + f * 4);
        *reinterpret_cast<float4*>(sm->cddc + (r >> 1) * GRPSTRIDE + (r & 1) * ROWOFF + f * 4) = v;
    }
    if (tid < SS)  sm->padh[tid] = hpad[(b * HH + h) * SS + tid];
    if (tid < KK)  sm->wv[tid]   = ltr_w[h * KK + tid];
    for (int i = tid; i < NCS; i += 256) sm->padc[i] = cpad[b * NCS + i];
    __syncthreads();

    // -------- his norms + cdd sumsq chunk0 --------
    if (tid < SS * 8) {
        int t = tid >> 3, p = tid & 7;
        float ss = 0.f;
        for (int e = p; e < EE; e += 8) {
            float v = sm->hisT[e * SS + t];
            ss = fmaf(v, v, ss);
        }
        ss += __shfl_down_sync(0xffffffffu, ss, 4);
        ss += __shfl_down_sync(0xffffffffu, ss, 2);
        ss += __shfl_down_sync(0xffffffffu, ss, 1);
        if (p == 0) sm->invh[t] = 1.0f / fmaxf(sqrtf(ss), 1e-12f);
    }
    for (int r = wid; r < NCS; r += 8) {
        const float* rb = sm->cddc + (r >> 1) * GRPSTRIDE + (r & 1) * ROWOFF;
        float ss = 0.f;
        for (int e = lane; e < F4C0 * 4; e += 32) {
            float v = rb[e];
            ss = fmaf(v, v, ss);
        }
        #pragma unroll
        for (int o = 16; o; o >>= 1) ss += __shfl_down_sync(0xffffffffu, ss, o);
        if (lane == 0) sm->sumc[r] = ss;
    }

    // -------- phase A chunk0 --------
    accum_chunk(sm->cddc + grpC * GRPSTRIDE, sm->hisT, ec, F4C0, 0, acc);
    __syncthreads();

    // -------- gather cdd chunk1 --------
    for (int i = tid; i < NCS * F4C1; i += 256) {
        int r = i / F4C1, f = i % F4C1;
        int tok = cand[b * NCS + r];
        float4 v = *reinterpret_cast<const float4*>(emb + (size_t)tok * EE + (F4C0 + f) * 4);
        *reinterpret_cast<float4*>(sm->cddc + (r >> 1) * GRPSTRIDE + (r & 1) * ROWOFF + f * 4) = v;
    }
    __syncthreads();

    // -------- cdd sumsq chunk1 -> invc --------
    for (int r = wid; r < NCS; r += 8) {
        const float* rb = sm->cddc + (r >> 1) * GRPSTRIDE + (r & 1) * ROWOFF;
        float ss = 0.f;
        for (int e = lane; e < F4C1 * 4; e += 32) {
            float v = rb[e];
            ss = fmaf(v, v, ss);
        }
        #pragma unroll
        for (int o = 16; o; o >>= 1) ss += __shfl_down_sync(0xffffffffu, ss, o);
        if (lane == 0) sm->invc[r] = 1.0f / fmaxf(sqrtf(sm->sumc[r] + ss), 1e-12f);
    }

    // -------- phase A chunk1 --------
    accum_chunk(sm->cddc + grpC * GRPSTRIDE, sm->hisT, ec, F4C1, F4C0, acc);
    __syncthreads();   // invc ready

    // -------- reduce over ec (lane -= 16, -= 8 -> lanes 0..7 hold totals) --------
    #pragma unroll
    for (int o = 16; o >= 8; o >>= 1) {
        #pragma unroll
        for (int r = 0; r < 2; ++r)
            #pragma unroll
            for (int p = 0; p < 10; ++p) {
                unsigned long long other = __shfl_down_sync(0xffffffffu, acc[r][p], o);
                float2 a = *reinterpret_cast<float2*>(&acc[r][p]);
                float2 bo = *reinterpret_cast<float2*>(&other);
                a.x += bo.x; a.y += bo.y;
                acc[r][p] = *reinterpret_cast<unsigned long long*>(&a);
            }
    }
    if (lane < 8 && grp < NGRP2) {
        int r0 = grp * 2;
        #pragma unroll
        for (int r = 0; r < 2; ++r) {
            float ic = sm->invc[r0 + r];
            #pragma unroll
            for (int p = 0; p < 10; ++p) {
                float2 a = *reinterpret_cast<float2*>(&acc[r][p]);
                int t0 = p * 2;
                sm->simbuf[(r0 + r) * SS + t0 + 0] = a.x * ic * sm->invh[t0 + 0];
                sm->simbuf[(r0 + r) * SS + t0 + 1] = a.y * ic * sm->invh[t0 + 1];
            }
        }
    }
    __syncthreads();

    // -------- phase B --------
    float contrib = 0.0f;
    if (tid < 200) {
        int cs = tid >> 1, kh = tid & 1;
        float ps[10];
        #pragma unroll
        for (int k = 0; k < 10; ++k) ps[k] = 0.f;
        for (int t = 0; t < SS; ++t) {
            float s  = sm->simbuf[cs * SS + t];
            float pt = sm->padh[t];
            #pragma unroll
            for (int k = 0; k < 10; ++k) {
                int kk = kh * 10 + k;
                float mu = -0.9f + 0.1f * (float)kk;
                float nc = (kh == 1 && k == 9) ? NC_LAST : NC_STD;
                float d = s - mu;
                ps[k] = fmaf(pt, ex2_approx(d * d * nc), ps[k]);
            }
        }
        float accw = 0.f;
        #pragma unroll
        for (int k = 0; k < 10; ++k) {
            float lp = __logf(fmaxf(ps[k], 1e-10f));
            accw = fmaf(lp, sm->wv[kh * 10 + k], accw);
        }
        contrib = accw * 0.01f * sm->padc[cs];
    }
    sm->cont[tid] = contrib;
    __syncthreads();

    if (tid < CC) {
        float s = 0.f;
        #pragma unroll 8
        for (int i = 0; i < 40; ++i) s += sm->cont[tid * 40 + i];
        g_partial[(b * HH + h) * CC + tid] = s;
    }
}

__global__ void knrm_final(const float* __restrict__ ltr_b, float* __restrict__ out)
{
    __shared__ float sc[BB * CC];
    int tid = threadIdx.x;
    if (tid < BB * CC) {
        int b = tid / CC, c = tid % CC;
        float s = ltr_b[0];
        for (int hh = 0; hh < HH; ++hh)
            s += g_partial[(b * HH + hh) * CC + c];
        sc[tid] = s;
    }
    __syncthreads();
    if (tid < BB * CC) {
        int b = tid / CC;
        float m = -1e30f;
        #pragma unroll
        for (int c2 = 0; c2 < CC; ++c2) m = fmaxf(m, sc[b * CC + c2]);
        float se = 0.f;
        #pragma unroll
        for (int c2 = 0; c2 < CC; ++c2) se += expf(sc[b * CC + c2] - m);
        out[tid] = sc[tid] - m - logf(se);
    }
}

extern "C" void kernel_launch(void* const* d_in, const int* in_sizes, int n_in,
                              void* d_out, int out_size)
{
    const int*   cand = (const int*)  d_in[0];
    const int*   clk  = (const int*)  d_in[1];
    const float* cpad = (const float*)d_in[2];
    const float* hpad = (const float*)d_in[3];
    const float* emb  = (const float*)d_in[4];
    const float* w    = (const float*)d_in[5];
    const float* bb   = (const float*)d_in[6];

    size_t smem = sizeof(Smem);
    cudaFuncSetAttribute(knrm_main, cudaFuncAttributeMaxDynamicSharedMemorySize, (int)smem);

    knrm_main<<<BB * HH, 256, smem>>>(cand, clk, cpad, hpad, emb, w);
    knrm_final<<<1, 192>>>(bb, (float*)d_out);
}

// round 7
// speedup vs baseline: 1.8665x; 1.2461x over previous
#include <cuda_runtime.h>
#include <cuda_bf16.h>
#include <cstdint>

#define BB 32
#define CC 5
#define HH 50
#define SS 20
#define EE 300
#define KK 20
#define F4N 75
#define NCS 100
#define NGRP2 50             // 2-row groups
#define ROWOFF 152           // floats: row1 offset within group
#define GRPSTRIDE 324        // 324 mod 32 = 4 -> conflict-free phase banks
#define F4C0 38              // chunk0 float4 per row (e 0..151)
#define F4C1 37              // chunk1 float4 per row (e 152..299)
#define NROWS_CDD (BB * CC * SS)     // 3200
#define NROWS_HIS (BB * HH * SS)     // 32000
#define NROWS_ALL (NROWS_CDD + NROWS_HIS)

#define NC_STD  (-72.134752f)
#define NC_LAST (-721347.52f)

struct Smem {
    float hisT[EE * SS];                // [e][t] 24000B
    float cddc[NGRP2 * GRPSTRIDE];      // 64800B
    float simbuf[NCS * SS];             // 8000B
    float padh[SS];
    float padc[NCS];
    float wv[KK];
    float cont[256];
};

__device__ float g_cddN[NROWS_CDD * EE];   // normalized candidate rows (3.84 MB)
__device__ float g_hisN[NROWS_HIS * EE];   // normalized clicked rows (38.4 MB)
__device__ float g_partial[BB * HH * CC];
__device__ unsigned int g_done;

__device__ __forceinline__ float ex2_approx(float x) {
    float r;
    asm("ex2.approx.ftz.f32 %0, %1;" : "=f"(r) : "f"(x));
    return r;
}
__device__ __forceinline__ void fma2(unsigned long long& acc,
                                     unsigned long long a, unsigned long long b) {
    asm("fma.rn.f32x2 %0, %1, %2, %0;" : "+l"(acc) : "l"(a), "l"(b));
}
__device__ __forceinline__ unsigned long long dupf(float x) {
    unsigned long long r;
    asm("mov.b64 %0, {%1, %1};" : "=l"(r) : "f"(x));
    return r;
}

// ---------------- prep: L2-normalize embedding rows into dense scratch ----------------
__global__ __launch_bounds__(256)
void knrm_prep(const int* __restrict__ cand, const int* __restrict__ clk,
               const float* __restrict__ emb)
{
    const int wid = threadIdx.x >> 5, lane = threadIdx.x & 31;
    const int row = blockIdx.x * 8 + wid;
    if (row >= NROWS_ALL) return;
    int tok;
    float* dst;
    if (row < NROWS_CDD) { tok = cand[row];             dst = g_cddN + (size_t)row * EE; }
    else                 { tok = clk[row - NROWS_CDD];  dst = g_hisN + (size_t)(row - NROWS_CDD) * EE; }
    const float* src = emb + (size_t)tok * EE;

    float4 v[3];
    float ss = 0.f;
    #pragma unroll
    for (int i = 0; i < 3; ++i) {
        int f = lane + i * 32;
        if (f < F4N) {
            v[i] = *reinterpret_cast<const float4*>(src + f * 4);
            ss = fmaf(v[i].x, v[i].x, ss);
            ss = fmaf(v[i].y, v[i].y, ss);
            ss = fmaf(v[i].z, v[i].z, ss);
            ss = fmaf(v[i].w, v[i].w, ss);
        }
    }
    #pragma unroll
    for (int o = 16; o; o >>= 1) ss += __shfl_xor_sync(0xffffffffu, ss, o);
    float inv = 1.0f / fmaxf(sqrtf(ss), 1e-12f);
    #pragma unroll
    for (int i = 0; i < 3; ++i) {
        int f = lane + i * 32;
        if (f < F4N) {
            float4 o4 = make_float4(v[i].x * inv, v[i].y * inv, v[i].z * inv, v[i].w * inv);
            *reinterpret_cast<float4*>(dst + f * 4) = o4;
        }
    }
}

// 2 rows x 20 t, f = ec + 4i over [0, f4cnt)
__device__ __forceinline__ void accum_chunk(const float* __restrict__ cbase,
                                            const float* __restrict__ hisT,
                                            int ec, int f4cnt, int fglob,
                                            unsigned long long (&acc)[2][10])
{
    for (int f = ec; f < f4cnt; f += 4) {
        float4 a0 = *reinterpret_cast<const float4*>(cbase + f * 4);
        float4 a1 = *reinterpret_cast<const float4*>(cbase + ROWOFF + f * 4);
        const float* hb = hisT + (fglob + f) * 4 * SS;
        #pragma unroll
        for (int j = 0; j < 4; ++j) {
            float v0 = (j == 0) ? a0.x : (j == 1) ? a0.y : (j == 2) ? a0.z : a0.w;
            float v1 = (j == 0) ? a1.x : (j == 1) ? a1.y : (j == 2) ? a1.z : a1.w;
            unsigned long long d0 = dupf(v0), d1 = dupf(v1);
            const ulonglong2* hp = reinterpret_cast<const ulonglong2*>(hb + j * SS);
            #pragma unroll
            for (int q = 0; q < 5; ++q) {
                ulonglong2 hv = hp[q];
                fma2(acc[0][q * 2 + 0], d0, hv.x);
                fma2(acc[0][q * 2 + 1], d0, hv.y);
                fma2(acc[1][q * 2 + 0], d1, hv.x);
                fma2(acc[1][q * 2 + 1], d1, hv.y);
            }
        }
    }
}

__global__ __launch_bounds__(256, 2)
void knrm_main(const float* __restrict__ cpad, const float* __restrict__ hpad,
               const float* __restrict__ ltr_w, const float* __restrict__ ltr_b,
               float* __restrict__ out)
{
    extern __shared__ float smraw[];
    Smem* sm = reinterpret_cast<Smem*>(smraw);
    const int tid = threadIdx.x;
    const int wid = tid >> 5, lane = tid & 31;
    const int b = blockIdx.x / HH;
    const int h = blockIdx.x % HH;

    const int ec = lane >> 3;
    const int g  = lane & 7;
    const int grp = wid * 8 + g;
    const int grpC = (grp < NGRP2) ? grp : (NGRP2 - 1);

    unsigned long long acc[2][10];
    #pragma unroll
    for (int r = 0; r < 2; ++r)
        #pragma unroll
        for (int p = 0; p < 10; ++p) acc[r][p] = 0ull;

    // -------- dense loads: hisT (transposed) + cdd chunk0 --------
    const float* hisSrc = g_hisN + (size_t)(b * HH + h) * SS * EE;
    const float* cddSrc = g_cddN + (size_t)b * NCS * EE;
    for (int i = tid; i < SS * F4N; i += 256) {
        int t = i / F4N, f = i % F4N;
        float4 v = *reinterpret_cast<const float4*>(hisSrc + t * EE + f * 4);
        sm->hisT[(f * 4 + 0) * SS + t] = v.x;
        sm->hisT[(f * 4 + 1) * SS + t] = v.y;
        sm->hisT[(f * 4 + 2) * SS + t] = v.z;
        sm->hisT[(f * 4 + 3) * SS + t] = v.w;
    }
    for (int i = tid; i < NCS * F4C0; i += 256) {
        int r = i / F4C0, f = i % F4C0;
        float4 v = *reinterpret_cast<const float4*>(cddSrc + r * EE + f * 4);
        *reinterpret_cast<float4*>(sm->cddc + (r >> 1) * GRPSTRIDE + (r & 1) * ROWOFF + f * 4) = v;
    }
    if (tid < SS)  sm->padh[tid] = hpad[(b * HH + h) * SS + tid];
    if (tid < KK)  sm->wv[tid]   = ltr_w[h * KK + tid];
    for (int i = tid; i < NCS; i += 256) sm->padc[i] = cpad[b * NCS + i];
    __syncthreads();

    // -------- phase A chunk0 --------
    accum_chunk(sm->cddc + grpC * GRPSTRIDE, sm->hisT, ec, F4C0, 0, acc);
    __syncthreads();

    // -------- load cdd chunk1 --------
    for (int i = tid; i < NCS * F4C1; i += 256) {
        int r = i / F4C1, f = i % F4C1;
        float4 v = *reinterpret_cast<const float4*>(cddSrc + r * EE + (F4C0 + f) * 4);
        *reinterpret_cast<float4*>(sm->cddc + (r >> 1) * GRPSTRIDE + (r & 1) * ROWOFF + f * 4) = v;
    }
    __syncthreads();

    // -------- phase A chunk1 --------
    accum_chunk(sm->cddc + grpC * GRPSTRIDE, sm->hisT, ec, F4C1, F4C0, acc);

    // -------- reduce over ec (16, 8 -> lanes 0..7) --------
    #pragma unroll
    for (int o = 16; o >= 8; o >>= 1) {
        #pragma unroll
        for (int r = 0; r < 2; ++r)
            #pragma unroll
            for (int p = 0; p < 10; ++p) {
                unsigned long long other = __shfl_down_sync(0xffffffffu, acc[r][p], o);
                float2 a = *reinterpret_cast<float2*>(&acc[r][p]);
                float2 bo = *reinterpret_cast<float2*>(&other);
                a.x += bo.x; a.y += bo.y;
                acc[r][p] = *reinterpret_cast<unsigned long long*>(&a);
            }
    }
    if (lane < 8 && grp < NGRP2) {
        int r0 = grp * 2;
        #pragma unroll
        for (int r = 0; r < 2; ++r) {
            #pragma unroll
            for (int p = 0; p < 10; ++p) {
                float2 a = *reinterpret_cast<float2*>(&acc[r][p]);
                int t0 = p * 2;
                sm->simbuf[(r0 + r) * SS + t0 + 0] = a.x;
                sm->simbuf[(r0 + r) * SS + t0 + 1] = a.y;
            }
        }
    }
    __syncthreads();

    // -------- phase B --------
    float contrib = 0.0f;
    if (tid < 200) {
        int cs = tid >> 1, kh = tid & 1;
        float ps[10];
        #pragma unroll
        for (int k = 0; k < 10; ++k) ps[k] = 0.f;
        for (int t = 0; t < SS; ++t) {
            float s  = sm->simbuf[cs * SS + t];
            float pt = sm->padh[t];
            #pragma unroll
            for (int k = 0; k < 10; ++k) {
                int kk = kh * 10 + k;
                float mu = -0.9f + 0.1f * (float)kk;
                float nc = (kh == 1 && k == 9) ? NC_LAST : NC_STD;
                float d = s - mu;
                ps[k] = fmaf(pt, ex2_approx(d * d * nc), ps[k]);
            }
        }
        float accw = 0.f;
        #pragma unroll
        for (int k = 0; k < 10; ++k) {
            float lp = __logf(fmaxf(ps[k], 1e-10f));
            accw = fmaf(lp, sm->wv[kh * 10 + k], accw);
        }
        contrib = accw * 0.01f * sm->padc[cs];
    }
    sm->cont[tid] = contrib;
    __syncthreads();

    if (tid < CC) {
        float s = 0.f;
        #pragma unroll 8
        for (int i = 0; i < 40; ++i) s += sm->cont[tid * 40 + i];
        g_partial[(b * HH + h) * CC + tid] = s;
    }
    __syncthreads();

    // -------- fused finalize: last block does h-sum + log_softmax --------
    __shared__ unsigned int isLast;
    if (tid == 0) {
        __threadfence();
        unsigned int v = atomicAdd(&g_done, 1u);
        isLast = (v == (unsigned)(BB * HH - 1)) ? 1u : 0u;
    }
    __syncthreads();
    if (isLast) {
        if (tid == 0) { g_done = 0; __threadfence(); }
        float* sc = sm->cont;   // reuse
        if (tid < BB * CC) {
            int bb2 = tid / CC, c = tid % CC;
            float s = ltr_b[0];
            for (int hh = 0; hh < HH; ++hh)
                s += g_partial[(bb2 * HH + hh) * CC + c];
            sc[tid] = s;
        }
        __syncthreads();
        if (tid < BB * CC) {
            int bb2 = tid / CC;
            float m = -1e30f;
            #pragma unroll
            for (int c2 = 0; c2 < CC; ++c2) m = fmaxf(m, sc[bb2 * CC + c2]);
            float se = 0.f;
            #pragma unroll
            for (int c2 = 0; c2 < CC; ++c2) se += expf(sc[bb2 * CC + c2] - m);
            out[tid] = sc[tid] - m - logf(se);
        }
    }
}

extern "C" void kernel_launch(void* const* d_in, const int* in_sizes, int n_in,
                              void* d_out, int out_size)
{
    const int*   cand = (const int*)  d_in[0];
    const int*   clk  = (const int*)  d_in[1];
    const float* cpad = (const float*)d_in[2];
    const float* hpad = (const float*)d_in[3];
    const float* emb  = (const float*)d_in[4];
    const float* w    = (const float*)d_in[5];
    const float* bb   = (const float*)d_in[6];

    size_t smem = sizeof(Smem);
    cudaFuncSetAttribute(knrm_main, cudaFuncAttributeMaxDynamicSharedMemorySize, (int)smem);

    knrm_prep<<<(NROWS_ALL + 7) / 8, 256>>>(cand, clk, emb);
    knrm_main<<<BB * HH, 256, smem>>>(cpad, hpad, w, bb, (float*)d_out);
}

// round 9
// speedup vs baseline: 1.9848x; 1.0634x over previous
#include <cuda_runtime.h>
#include <cuda_bf16.h>
#include <cstdint>

#define BB 32
#define CC 5
#define HH 50
#define SS 20
#define EE 300
#define KK 20
#define F4N 75
#define NCS 100
#define THREADS 224
#define NGRP2 50             // 2-row groups
#define ROWOFF 76            // floats: row1 offset within group (19 float4)
#define GRPSTRIDE 164        // 164 mod 32 = 4 -> conflict-free phase banks
#define NCHUNK 4
#define NROWS_CDD (BB * CC * SS)     // 3200
#define NROWS_HIS (BB * HH * SS)     // 32000
#define NROWS_ALL (NROWS_CDD + NROWS_HIS)

#define NC_STD  (-72.134752f)
#define NC_LAST (-721347.52f)

__device__ __constant__ int c_f4cnt[NCHUNK] = {19, 19, 19, 18};
__device__ __constant__ int c_f4off[NCHUNK] = {0, 19, 38, 57};

struct Smem {
    float hisT[EE * SS];                // 24000B
    float cddc[NGRP2 * GRPSTRIDE];      // 32800B
    float simbuf[NCS * SS];             // 8000B
    float padh[SS];
    float padc[NCS];
    float wv[KK];
    float cont[THREADS];
};

__device__ float g_cddN[NROWS_CDD * EE];
__device__ float g_hisN[NROWS_HIS * EE];
__device__ float g_partial[BB * HH * CC];
__device__ unsigned int g_done;

__device__ __forceinline__ float ex2_approx(float x) {
    float r;
    asm("ex2.approx.ftz.f32 %0, %1;" : "=f"(r) : "f"(x));
    return r;
}
__device__ __forceinline__ void fma2(unsigned long long& acc,
                                     unsigned long long a, unsigned long long b) {
    asm("fma.rn.f32x2 %0, %1, %2, %0;" : "+l"(acc) : "l"(a), "l"(b));
}
__device__ __forceinline__ unsigned long long dupf(float x) {
    unsigned long long r;
    asm("mov.b64 %0, {%1, %1};" : "=l"(r) : "f"(x));
    return r;
}

// ---------------- prep: L2-normalize embedding rows into dense scratch ----------------
__global__ __launch_bounds__(256)
void knrm_prep(const int* __restrict__ cand, const int* __restrict__ clk,
               const float* __restrict__ emb)
{
    const int wid = threadIdx.x >> 5, lane = threadIdx.x & 31;
    const int row = blockIdx.x * 8 + wid;
    if (row >= NROWS_ALL) return;
    int tok;
    float* dst;
    if (row < NROWS_CDD) { tok = cand[row];             dst = g_cddN + (size_t)row * EE; }
    else                 { tok = clk[row - NROWS_CDD];  dst = g_hisN + (size_t)(row - NROWS_CDD) * EE; }
    const float* src = emb + (size_t)tok * EE;

    float4 v[3];
    float ss = 0.f;
    #pragma unroll
    for (int i = 0; i < 3; ++i) {
        int f = lane + i * 32;
        if (f < F4N) {
            v[i] = *reinterpret_cast<const float4*>(src + f * 4);
            ss = fmaf(v[i].x, v[i].x, ss);
            ss = fmaf(v[i].y, v[i].y, ss);
            ss = fmaf(v[i].z, v[i].z, ss);
            ss = fmaf(v[i].w, v[i].w, ss);
        }
    }
    #pragma unroll
    for (int o = 16; o; o >>= 1) ss += __shfl_xor_sync(0xffffffffu, ss, o);
    float inv = 1.0f / fmaxf(sqrtf(ss), 1e-12f);
    #pragma unroll
    for (int i = 0; i < 3; ++i) {
        int f = lane + i * 32;
        if (f < F4N) {
            float4 o4 = make_float4(v[i].x * inv, v[i].y * inv, v[i].z * inv, v[i].w * inv);
            *reinterpret_cast<float4*>(dst + f * 4) = o4;
        }
    }
}

// 2 rows x 20 t, f = ec + 4i over [0, f4cnt); his e-index = (fglob + f)*4 + j
__device__ __forceinline__ void accum_chunk(const float* __restrict__ cbase,
                                            const float* __restrict__ hisT,
                                            int ec, int f4cnt, int fglob,
                                            unsigned long long (&acc)[2][10])
{
    for (int f = ec; f < f4cnt; f += 4) {
        float4 a0 = *reinterpret_cast<const float4*>(cbase + f * 4);
        float4 a1 = *reinterpret_cast<const float4*>(cbase + ROWOFF + f * 4);
        const float* hb = hisT + (fglob + f) * 4 * SS;
        #pragma unroll
        for (int j = 0; j < 4; ++j) {
            float v0 = (j == 0) ? a0.x : (j == 1) ? a0.y : (j == 2) ? a0.z : a0.w;
            float v1 = (j == 0) ? a1.x : (j == 1) ? a1.y : (j == 2) ? a1.z : a1.w;
            unsigned long long d0 = dupf(v0), d1 = dupf(v1);
            const ulonglong2* hp = reinterpret_cast<const ulonglong2*>(hb + j * SS);
            #pragma unroll
            for (int q = 0; q < 5; ++q) {
                ulonglong2 hv = hp[q];
                fma2(acc[0][q * 2 + 0], d0, hv.x);
                fma2(acc[0][q * 2 + 1], d0, hv.y);
                fma2(acc[1][q * 2 + 0], d1, hv.x);
                fma2(acc[1][q * 2 + 1], d1, hv.y);
            }
        }
    }
}

__global__ __launch_bounds__(THREADS, 3)
void knrm_main(const float* __restrict__ cpad, const float* __restrict__ hpad,
               const float* __restrict__ ltr_w, const float* __restrict__ ltr_b,
               float* __restrict__ out)
{
    extern __shared__ float smraw[];
    Smem* sm = reinterpret_cast<Smem*>(smraw);
    const int tid = threadIdx.x;
    const int wid = tid >> 5, lane = tid & 31;
    const int b = blockIdx.x / HH;
    const int h = blockIdx.x % HH;

    const int ec = lane >> 3;
    const int g  = lane & 7;
    const int grp = wid * 8 + g;
    const int grpC = (grp < NGRP2) ? grp : (NGRP2 - 1);

    unsigned long long acc[2][10];
    #pragma unroll
    for (int r = 0; r < 2; ++r)
        #pragma unroll
        for (int p = 0; p < 10; ++p) acc[r][p] = 0ull;

    // -------- preamble: hisT (transposed) + cdd chunk0 + pads --------
    const float* hisSrc = g_hisN + (size_t)(b * HH + h) * SS * EE;
    const float* cddSrc = g_cddN + (size_t)b * NCS * EE;
    for (int i = tid; i < SS * F4N; i += THREADS) {
        int t = i / F4N, f = i % F4N;
        float4 v = *reinterpret_cast<const float4*>(hisSrc + t * EE + f * 4);
        sm->hisT[(f * 4 + 0) * SS + t] = v.x;
        sm->hisT[(f * 4 + 1) * SS + t] = v.y;
        sm->hisT[(f * 4 + 2) * SS + t] = v.z;
        sm->hisT[(f * 4 + 3) * SS + t] = v.w;
    }
    for (int i = tid; i < NCS * 19; i += THREADS) {
        int r = i / 19, f = i % 19;
        float4 v = *reinterpret_cast<const float4*>(cddSrc + r * EE + f * 4);
        *reinterpret_cast<float4*>(sm->cddc + (r >> 1) * GRPSTRIDE + (r & 1) * ROWOFF + f * 4) = v;
    }
    if (tid < SS)  sm->padh[tid] = hpad[(b * HH + h) * SS + tid];
    if (tid < KK)  sm->wv[tid]   = ltr_w[h * KK + tid];
    for (int i = tid; i < NCS; i += THREADS) sm->padc[i] = cpad[b * NCS + i];
    __syncthreads();

    // -------- chunked phase A --------
    #pragma unroll
    for (int k = 0; k < NCHUNK; ++k) {
        accum_chunk(sm->cddc + grpC * GRPSTRIDE, sm->hisT, ec, c_f4cnt[k], c_f4off[k], acc);
        __syncthreads();                  // all reads of chunk k done
        if (k + 1 < NCHUNK) {
            int cnt = c_f4cnt[k + 1], off = c_f4off[k + 1];
            for (int i = tid; i < NCS * cnt; i += THREADS) {
                int r = i / cnt, f = i % cnt;
                float4 v = *reinterpret_cast<const float4*>(cddSrc + r * EE + (off + f) * 4);
                *reinterpret_cast<float4*>(sm->cddc + (r >> 1) * GRPSTRIDE + (r & 1) * ROWOFF + f * 4) = v;
            }
            __syncthreads();              // chunk k+1 visible
        }
    }

    // -------- reduce over ec (16, 8 -> lanes 0..7) --------
    #pragma unroll
    for (int o = 16; o >= 8; o >>= 1) {
        #pragma unroll
        for (int r = 0; r < 2; ++r)
            #pragma unroll
            for (int p = 0; p < 10; ++p) {
                unsigned long long other = __shfl_down_sync(0xffffffffu, acc[r][p], o);
                float2 a = *reinterpret_cast<float2*>(&acc[r][p]);
                float2 bo = *reinterpret_cast<float2*>(&other);
                a.x += bo.x; a.y += bo.y;
                acc[r][p] = *reinterpret_cast<unsigned long long*>(&a);
            }
    }
    if (lane < 8 && grp < NGRP2) {
        int r0 = grp * 2;
        #pragma unroll
        for (int r = 0; r < 2; ++r) {
            #pragma unroll
            for (int p = 0; p < 10; ++p) {
                float2 a = *reinterpret_cast<float2*>(&acc[r][p]);
                int t0 = p * 2;
                sm->simbuf[(r0 + r) * SS + t0 + 0] = a.x;
                sm->simbuf[(r0 + r) * SS + t0 + 1] = a.y;
            }
        }
    }
    __syncthreads();

    // -------- phase B --------
    float contrib = 0.0f;
    if (tid < 200) {
        int cs = tid >> 1, kh = tid & 1;
        float ps[10];
        #pragma unroll
        for (int k = 0; k < 10; ++k) ps[k] = 0.f;
        for (int t = 0; t < SS; ++t) {
            float s  = sm->simbuf[cs * SS + t];
            float pt = sm->padh[t];
            #pragma unroll
            for (int k = 0; k < 10; ++k) {
                int kk = kh * 10 + k;
                float mu = -0.9f + 0.1f * (float)kk;
                float nc = (kh == 1 && k == 9) ? NC_LAST : NC_STD;
                float d = s - mu;
                ps[k] = fmaf(pt, ex2_approx(d * d * nc), ps[k]);
            }
        }
        float accw = 0.f;
        #pragma unroll
        for (int k = 0; k < 10; ++k) {
            float lp = __logf(fmaxf(ps[k], 1e-10f));
            accw = fmaf(lp, sm->wv[kh * 10 + k], accw);
        }
        contrib = accw * 0.01f * sm->padc[cs];
    }
    sm->cont[tid] = contrib;
    __syncthreads();

    if (tid < CC) {
        float s = 0.f;
        #pragma unroll 8
        for (int i = 0; i < 40; ++i) s += sm->cont[tid * 40 + i];
        g_partial[(b * HH + h) * CC + tid] = s;
    }
    __syncthreads();

    // -------- fused finalize --------
    __shared__ unsigned int isLast;
    if (tid == 0) {
        __threadfence();
        unsigned int v = atomicAdd(&g_done, 1u);
        isLast = (v == (unsigned)(BB * HH - 1)) ? 1u : 0u;
    }
    __syncthreads();
    if (isLast) {
        if (tid == 0) { g_done = 0; __threadfence(); }
        float* sc = sm->cont;
        if (tid < BB * CC) {
            int bb2 = tid / CC, c = tid % CC;
            float s = ltr_b[0];
            for (int hh = 0; hh < HH; ++hh)
                s += g_partial[(bb2 * HH + hh) * CC + c];
            sc[tid] = s;
        }
        __syncthreads();
        if (tid < BB * CC) {
            int bb2 = tid / CC;
            float m = -1e30f;
            #pragma unroll
            for (int c2 = 0; c2 < CC; ++c2) m = fmaxf(m, sc[bb2 * CC + c2]);
            float se = 0.f;
            #pragma unroll
            for (int c2 = 0; c2 < CC; ++c2) se += expf(sc[bb2 * CC + c2] - m);
            out[tid] = sc[tid] - m - logf(se);
        }
    }
}

extern "C" void kernel_launch(void* const* d_in, const int* in_sizes, int n_in,
                              void* d_out, int out_size)
{
    const int*   cand = (const int*)  d_in[0];
    const int*   clk  = (const int*)  d_in[1];
    const float* cpad = (const float*)d_in[2];
    const float* hpad = (const float*)d_in[3];
    const float* emb  = (const float*)d_in[4];
    const float* w    = (const float*)d_in[5];
    const float* bb   = (const float*)d_in[6];

    size_t smem = sizeof(Smem);
    cudaFuncSetAttribute(knrm_main, cudaFuncAttributeMaxDynamicSharedMemorySize, (int)smem);

    knrm_prep<<<(NROWS_ALL + 7) / 8, 256>>>(cand, clk, emb);
    knrm_main<<<BB * HH, THREADS, smem>>>(cpad, hpad, w, bb, (float*)d_out);
}